// round 2
// baseline (speedup 1.0000x reference)
#include <cuda_runtime.h>

// LSTM scan: T=2048 steps, B=2048 batch, IN=5, H=10.
// Thread = (batch, hidden unit). 160 threads/block = 16 batches x 10 h.
// Grid = 128 blocks covering all 2048 batches.
// Gates computed with packed f32x2 FMAs; h exchanged via double-buffered smem.

#define T_STEPS 2048
#define BATCH   2048
#define IN_DIM  5
#define HID     10
#define BB      16                 // batches per block
#define NTHREADS (BB * HID)        // 160

__device__ __forceinline__ unsigned long long pack2(float lo, float hi) {
    unsigned long long r;
    asm("mov.b64 %0, {%1, %2};" : "=l"(r) : "f"(lo), "f"(hi));
    return r;
}
__device__ __forceinline__ void unpack2(unsigned long long v, float& lo, float& hi) {
    asm("mov.b64 {%0, %1}, %2;" : "=f"(lo), "=f"(hi) : "l"(v));
}
__device__ __forceinline__ unsigned long long ffma2(unsigned long long a,
                                                    unsigned long long b,
                                                    unsigned long long c) {
    unsigned long long d;
    asm("fma.rn.f32x2 %0, %1, %2, %3;" : "=l"(d) : "l"(a), "l"(b), "l"(c));
    return d;
}
// sigmoid / tanh via MUFU.EX2 + MUFU.RCP (accurate enough for 1e-3 rel-err
// across the 2048-step recursion; tanh.approx is a later-round experiment).
__device__ __forceinline__ float fsig(float z) {
    float e = __expf(-z);
    return __fdividef(1.0f, 1.0f + e);
}
__device__ __forceinline__ float ftanh(float z) {
    float e = __expf(-2.0f * z);
    return __fdividef(2.0f, 1.0f + e) - 1.0f;
}

__global__ void __launch_bounds__(NTHREADS, 1) lstm_scan_kernel(
    const float* __restrict__ x,     // [T, B, IN]
    const float* __restrict__ hx0,   // [B, H]
    const float* __restrict__ cx0,   // [B, H]
    const float* __restrict__ Wih,   // [4H, IN]
    const float* __restrict__ Whh,   // [4H, H]
    const float* __restrict__ bih,   // [4H]
    const float* __restrict__ bhh,   // [4H]
    float* __restrict__ out)         // [T*B, H]
{
    // Double-buffered h. Row = 10 floats = 40 bytes -> every row 8B-aligned,
    // so (h0,h1),(h2,h3),... load as LDS.64 pairs directly.
    __shared__ __align__(16) float hb[2][BB][HID];

    const int tid = threadIdx.x;
    const int bl  = tid / HID;        // local batch 0..15
    const int h   = tid % HID;        // hidden unit 0..9
    const int b   = blockIdx.x * BB + bl;

    // Pack weights for v-layout [x0..x4, 0, h0..h9] (16 slots -> 8 f32x2).
    unsigned long long wp[4][8];
    float bias[4];
#pragma unroll
    for (int g = 0; g < 4; g++) {
        const int r = g * HID + h;
        float wv[16];
#pragma unroll
        for (int k = 0; k < IN_DIM; k++) wv[k] = Wih[r * IN_DIM + k];
        wv[5] = 0.0f;                 // pad slot (weight 0 so pad x is inert)
#pragma unroll
        for (int j = 0; j < HID; j++) wv[6 + j] = Whh[r * HID + j];
#pragma unroll
        for (int p = 0; p < 8; p++) wp[g][p] = pack2(wv[2 * p], wv[2 * p + 1]);
        bias[g] = bih[r] + bhh[r];
    }

    float c = cx0[(size_t)b * HID + h];
    hb[0][bl][h] = hx0[(size_t)b * HID + h];
    __syncthreads();

    const float* xp = x + (size_t)b * IN_DIM;            // x[t=0, b, 0]
    float*       op = out + (size_t)b * HID + h;         // out[row=b, h] at t=0

    int cur = 0;
#pragma unroll 1
    for (int t = 0; t < T_STEPS; t++) {
        // x[t, b, 0..4]
        const float x0 = __ldg(xp + 0);
        const float x1 = __ldg(xp + 1);
        const float x2 = __ldg(xp + 2);
        const float x3 = __ldg(xp + 3);
        const float x4 = __ldg(xp + 4);

        unsigned long long v[8];
        v[0] = pack2(x0, x1);
        v[1] = pack2(x2, x3);
        v[2] = pack2(x4, 0.0f);
        const unsigned long long* hq =
            reinterpret_cast<const unsigned long long*>(hb[cur][bl]);
#pragma unroll
        for (int p = 0; p < 5; p++) v[3 + p] = hq[p];

        float gate[4];
#pragma unroll
        for (int g = 0; g < 4; g++) {
            unsigned long long acc = pack2(bias[g], 0.0f);
#pragma unroll
            for (int p = 0; p < 8; p++) acc = ffma2(wp[g][p], v[p], acc);
            float lo, hi;
            unpack2(acc, lo, hi);
            gate[g] = lo + hi;
        }

        const float is = fsig(gate[0]);
        const float fs = fsig(gate[1]);
        const float gt = ftanh(gate[2]);
        const float os = fsig(gate[3]);
        c = fs * c + is * gt;
        const float hn = os * ftanh(c);

        hb[cur ^ 1][bl][h] = hn;   // next step's h
        *op = hn;                  // coalesced: tid maps to contiguous floats
        __syncthreads();

        cur ^= 1;
        xp += BATCH * IN_DIM;
        op += (size_t)BATCH * HID;
    }
}

extern "C" void kernel_launch(void* const* d_in, const int* in_sizes, int n_in,
                              void* d_out, int out_size) {
    (void)in_sizes; (void)n_in; (void)out_size;
    const float* x   = (const float*)d_in[0];
    const float* hx0 = (const float*)d_in[1];
    const float* cx0 = (const float*)d_in[2];
    const float* Wih = (const float*)d_in[3];
    const float* Whh = (const float*)d_in[4];
    const float* bih = (const float*)d_in[5];
    const float* bhh = (const float*)d_in[6];
    float* out = (float*)d_out;

    lstm_scan_kernel<<<BATCH / BB, NTHREADS>>>(x, hx0, cx0, Wih, Whh, bih, bhh, out);
}

// round 3
// speedup vs baseline: 4.3190x; 4.3190x over previous
#include <cuda_runtime.h>

// LSTM scan: T=2048, B=2048, IN=5, H=10.
// R2: (1) 4-deep register prefetch of x hides DRAM latency (R1 killer),
//     (2) warp-confined batches: 3 batches on 30 lanes/warp, h exchanged by
//         SHFL (no smem, no __syncthreads),
//     (3) activations via MUFU.TANH (tanh.approx.f32).
// Gates computed with packed f32x2 FMAs; weights register-resident.

#define T_STEPS 2048
#define BATCH   2048
#define IN_DIM  5
#define HID     10
#define BPW     3                              // batches per warp (30 lanes)
#define NBLOCKS ((BATCH + BPW - 1) / BPW)      // 683 one-warp blocks
#define PF      4                              // x prefetch depth (divides T)

__device__ __forceinline__ unsigned long long pack2(float lo, float hi) {
    unsigned long long r;
    asm("mov.b64 %0, {%1, %2};" : "=l"(r) : "f"(lo), "f"(hi));
    return r;
}
__device__ __forceinline__ void unpack2(unsigned long long v, float& lo, float& hi) {
    asm("mov.b64 {%0, %1}, %2;" : "=f"(lo), "=f"(hi) : "l"(v));
}
__device__ __forceinline__ unsigned long long ffma2(unsigned long long a,
                                                    unsigned long long b,
                                                    unsigned long long c) {
    unsigned long long d;
    asm("fma.rn.f32x2 %0, %1, %2, %3;" : "=l"(d) : "l"(a), "l"(b), "l"(c));
    return d;
}
__device__ __forceinline__ float tanha(float z) {
    float r;
    asm("tanh.approx.f32 %0, %1;" : "=f"(r) : "f"(z));
    return r;
}
// sigmoid(z) = 0.5 + 0.5*tanh(0.5*z): one MUFU.TANH + 2 FMA
__device__ __forceinline__ float fsig(float z) {
    return fmaf(0.5f, tanha(0.5f * z), 0.5f);
}

__global__ void __launch_bounds__(32, 1) lstm_scan_kernel(
    const float* __restrict__ x,     // [T, B, IN]
    const float* __restrict__ hx0,   // [B, H]
    const float* __restrict__ cx0,   // [B, H]
    const float* __restrict__ Wih,   // [4H, IN]
    const float* __restrict__ Whh,   // [4H, H]
    const float* __restrict__ bih,   // [4H]
    const float* __restrict__ bhh,   // [4H]
    float* __restrict__ out)         // [T*B, H]
{
    const int lane = threadIdx.x;
    const int g    = lane / HID;          // batch slot within warp (0..3)
    const int h    = lane % HID;          // hidden unit 0..9
    const int base = g * HID;             // first lane of this batch's group

    const int  b_raw  = blockIdx.x * BPW + g;
    const bool active = (g < BPW) && (b_raw < BATCH);
    const int  b      = active ? b_raw : (BATCH - 1);   // clamp for safe loads

    // Pack weights for v-layout [x0..x4, 0, h0..h9] (16 slots -> 8 f32x2).
    unsigned long long wp[4][8];
    float bias[4];
#pragma unroll
    for (int q = 0; q < 4; q++) {
        const int r = q * HID + h;
        float wv[16];
#pragma unroll
        for (int k = 0; k < IN_DIM; k++) wv[k] = Wih[r * IN_DIM + k];
        wv[5] = 0.0f;                                    // pad slot
#pragma unroll
        for (int j = 0; j < HID; j++) wv[6 + j] = Whh[r * HID + j];
#pragma unroll
        for (int p = 0; p < 8; p++) wp[q][p] = pack2(wv[2 * p], wv[2 * p + 1]);
        bias[q] = bih[r] + bhh[r];
    }

    float c    = cx0[(size_t)b * HID + h];
    float hcur = hx0[(size_t)b * HID + h];   // own h value; peers fetched via shfl

    // Preload x for steps 0..PF-1 into the register ring.
    float xr[PF][IN_DIM];
#pragma unroll
    for (int d = 0; d < PF; d++) {
        const float* pp = x + ((size_t)d * BATCH + b) * IN_DIM;
#pragma unroll
        for (int k = 0; k < IN_DIM; k++) xr[d][k] = __ldg(pp + k);
    }

    float* op = out + (size_t)b * HID + h;   // out[(t*B + b)*H + h] at t=0

#pragma unroll 1
    for (int t = 0; t < T_STEPS; t += PF) {
#pragma unroll
        for (int d = 0; d < PF; d++) {
            // Consume this slot's x, then immediately issue the prefetch for
            // step t+d+PF (result needed PF steps later -> latency hidden).
            const float x0 = xr[d][0], x1 = xr[d][1], x2 = xr[d][2];
            const float x3 = xr[d][3], x4 = xr[d][4];
            {
                int tn = t + d + PF;
                if (tn > T_STEPS - 1) tn = T_STEPS - 1;  // harmless dup load
                const float* pp = x + ((size_t)tn * BATCH + b) * IN_DIM;
#pragma unroll
                for (int k = 0; k < IN_DIM; k++) xr[d][k] = __ldg(pp + k);
            }

            // Gather the 10 h values of this batch from peer lanes.
            float hv[HID];
#pragma unroll
            for (int j = 0; j < HID; j++)
                hv[j] = __shfl_sync(0xFFFFFFFFu, hcur, base + j);

            unsigned long long v[8];
            v[0] = pack2(x0, x1);
            v[1] = pack2(x2, x3);
            v[2] = pack2(x4, 0.0f);
#pragma unroll
            for (int p = 0; p < 5; p++) v[3 + p] = pack2(hv[2 * p], hv[2 * p + 1]);

            float gate[4];
#pragma unroll
            for (int q = 0; q < 4; q++) {
                unsigned long long acc = pack2(bias[q], 0.0f);
#pragma unroll
                for (int p = 0; p < 8; p++) acc = ffma2(wp[q][p], v[p], acc);
                float lo, hi;
                unpack2(acc, lo, hi);
                gate[q] = lo + hi;
            }

            const float is = fsig(gate[0]);
            const float fs = fsig(gate[1]);
            const float gt = tanha(gate[2]);
            const float os = fsig(gate[3]);
            c = fs * c + is * gt;
            const float hn = os * tanha(c);
            hcur = hn;

            if (active) *op = hn;
            op += (size_t)BATCH * HID;
        }
    }
}

extern "C" void kernel_launch(void* const* d_in, const int* in_sizes, int n_in,
                              void* d_out, int out_size) {
    (void)in_sizes; (void)n_in; (void)out_size;
    const float* x   = (const float*)d_in[0];
    const float* hx0 = (const float*)d_in[1];
    const float* cx0 = (const float*)d_in[2];
    const float* Wih = (const float*)d_in[3];
    const float* Whh = (const float*)d_in[4];
    const float* bih = (const float*)d_in[5];
    const float* bhh = (const float*)d_in[6];
    float* out = (float*)d_out;

    lstm_scan_kernel<<<NBLOCKS, 32>>>(x, hx0, cx0, Wih, Whh, bih, bhh, out);
}